// round 13
// baseline (speedup 1.0000x reference)
#include <cuda_runtime.h>
#include <cuda_bf16.h>
#include <cstdint>

#define OUT_DIM 11008
#define IN_DIM  4096
#define RANK    128
#define NG      32
#define NTOK    64
#define NPACK   1024
#define KSPLIT  8

// -------- device scratch --------
__device__ float g_Wf[(size_t)OUT_DIM * IN_DIM];
__device__ int   g_rowmax[OUT_DIM];
__device__ float g_rcpw[OUT_DIM];
__device__ int   g_xq[NTOK * NPACK];
__device__ float g_scale_x[NTOK];
__device__ __nv_bfloat16 g_up_hi[(size_t)OUT_DIM * RANK];
__device__ __nv_bfloat16 g_up_lo[(size_t)OUT_DIM * RANK];
__device__ __nv_bfloat16 g_dT_hi[(size_t)IN_DIM * RANK];
__device__ __nv_bfloat16 g_dT_lo[(size_t)IN_DIM * RANK];
__device__ int   g_acc[NTOK * OUT_DIM];

// -------- helpers --------
__device__ __forceinline__ uint32_t smem_to_u32(const void* p) {
    uint32_t a;
    asm("{ .reg .u64 t; cvta.to.shared.u64 t, %1; cvt.u32.u64 %0, t; }" : "=r"(a) : "l"(p));
    return a;
}
__device__ __forceinline__ void ldsm_x4(uint32_t (&r)[4], uint32_t addr) {
    asm volatile("ldmatrix.sync.aligned.m8n8.x4.shared.b16 {%0,%1,%2,%3}, [%4];"
        : "=r"(r[0]), "=r"(r[1]), "=r"(r[2]), "=r"(r[3]) : "r"(addr));
}
__device__ __forceinline__ void mma_bf16(float (&c)[4], const uint32_t (&a)[4],
                                         uint32_t b0, uint32_t b1) {
    asm volatile("mma.sync.aligned.m16n8k16.row.col.f32.bf16.bf16.f32 "
        "{%0,%1,%2,%3}, {%4,%5,%6,%7}, {%8,%9}, {%0,%1,%2,%3};"
        : "+f"(c[0]), "+f"(c[1]), "+f"(c[2]), "+f"(c[3])
        : "r"(a[0]), "r"(a[1]), "r"(a[2]), "r"(a[3]), "r"(b0), "r"(b1));
}
__device__ __forceinline__ void mma_s8(int (&c)[4], const uint32_t (&a)[4],
                                       uint32_t b0, uint32_t b1) {
    asm volatile("mma.sync.aligned.m16n8k32.row.col.s32.s8.s8.s32 "
        "{%0,%1,%2,%3}, {%4,%5,%6,%7}, {%8,%9}, {%0,%1,%2,%3};"
        : "+r"(c[0]), "+r"(c[1]), "+r"(c[2]), "+r"(c[3])
        : "r"(a[0]), "r"(a[1]), "r"(a[2]), "r"(a[3]), "r"(b0), "r"(b1));
}
// swizzle for 128B-pitch rows: XOR 16B-chunk index by row%8 (self-inverse)
__device__ __forceinline__ uint32_t swz128(uint32_t b) { return b ^ (((b >> 7) & 7u) << 4); }
// B-column permutation within each 32-row group: logical L = 8p+2n+b -> smem row 8n+2p+b.
// Lane p of a quad then owns logical columns [8p, 8p+8) contiguously in the epilogue.
__device__ __forceinline__ int bperm(int r) {
    return (r & ~31) | (((r >> 1) & 3) * 8 + ((r >> 3) & 3) * 2 + (r & 1));
}

__device__ __forceinline__ int quant_pack4_mul(float4 v, float rcp) {
    int q0 = __float2int_rn(v.x * rcp);
    int q1 = __float2int_rn(v.y * rcp);
    int q2 = __float2int_rn(v.z * rcp);
    int q3 = __float2int_rn(v.w * rcp);
    return (q0 & 0xff) | ((q1 & 0xff) << 8) | ((q2 & 0xff) << 16) | (q3 << 24);
}

// ==================== k1: quantize x, zero rowmax + g_acc ====================
__global__ void k1_quant_x(const float* __restrict__ x) {
    __shared__ __align__(16) float s_x[IN_DIM];
    __shared__ float s_red[256];
    const int t = blockIdx.x;
    const int tid = threadIdx.x;
    {
        int g = t * 256 + tid;
        if (g < OUT_DIM) g_rowmax[g] = 0;
        for (int z = g; z < NTOK * OUT_DIM; z += 64 * 256) g_acc[z] = 0;
    }
    const float4* xr = reinterpret_cast<const float4*>(x + (size_t)t * IN_DIM);
    float m = 0.f;
    #pragma unroll
    for (int j = 0; j < 4; ++j) {
        int idx = tid + j * 256;
        float4 v = xr[idx];
        reinterpret_cast<float4*>(s_x)[idx] = v;
        m = fmaxf(m, fmaxf(fmaxf(fabsf(v.x), fabsf(v.y)), fmaxf(fabsf(v.z), fabsf(v.w))));
    }
    s_red[tid] = m;
    __syncthreads();
    for (int s = 128; s > 0; s >>= 1) {
        if (tid < s) s_red[tid] = fmaxf(s_red[tid], s_red[tid + s]);
        __syncthreads();
    }
    const float sx = __fdiv_rn(s_red[0], 127.0f);
    if (tid == 0) g_scale_x[t] = sx;
    #pragma unroll
    for (int j = 0; j < 4; ++j) {
        int idx = tid + j * 256;
        float4 v = reinterpret_cast<const float4*>(s_x)[idx];
        int q0 = __float2int_rn(__fdiv_rn(v.x, sx));
        int q1 = __float2int_rn(__fdiv_rn(v.y, sx));
        int q2 = __float2int_rn(__fdiv_rn(v.z, sx));
        int q3 = __float2int_rn(__fdiv_rn(v.w, sx));
        g_xq[t * NPACK + idx] = (q0 & 0xff) | ((q1 & 0xff) << 8) | ((q2 & 0xff) << 16) | (q3 << 24);
    }
}

// ==================== prep: bf16 two-term splits ====================
__global__ void kp_split_up(const float* __restrict__ up) {
    int idx = blockIdx.x * 256 + threadIdx.x;
    if (idx < OUT_DIM * RANK / 4) {
        float4 v = reinterpret_cast<const float4*>(up)[idx];
        float f[4] = {v.x, v.y, v.z, v.w};
        uint32_t hi[2], lo[2];
        #pragma unroll
        for (int k = 0; k < 2; ++k) {
            __nv_bfloat16 h0 = __float2bfloat16(f[k*2+0]);
            __nv_bfloat16 h1 = __float2bfloat16(f[k*2+1]);
            __nv_bfloat16 l0 = __float2bfloat16(f[k*2+0] - __bfloat162float(h0));
            __nv_bfloat16 l1 = __float2bfloat16(f[k*2+1] - __bfloat162float(h1));
            hi[k] = (uint32_t)__bfloat16_as_ushort(h0) | ((uint32_t)__bfloat16_as_ushort(h1) << 16);
            lo[k] = (uint32_t)__bfloat16_as_ushort(l0) | ((uint32_t)__bfloat16_as_ushort(l1) << 16);
        }
        reinterpret_cast<uint2*>(g_up_hi)[idx] = make_uint2(hi[0], hi[1]);
        reinterpret_cast<uint2*>(g_up_lo)[idx] = make_uint2(lo[0], lo[1]);
    }
}

__global__ void kp_split_downT(const float* __restrict__ down) {
    __shared__ float t[32][33];
    const int bx = blockIdx.x, by = blockIdx.y;
    const int tx = threadIdx.x, ty = threadIdx.y;
    #pragma unroll
    for (int k = 0; k < 4; ++k)
        t[ty + k * 8][tx] = down[(size_t)(by * 32 + ty + k * 8) * IN_DIM + bx * 32 + tx];
    __syncthreads();
    #pragma unroll
    for (int k = 0; k < 4; ++k) {
        int i = bx * 32 + ty + k * 8;
        int r = by * 32 + tx;
        float v = t[tx][ty + k * 8];
        __nv_bfloat16 h = __float2bfloat16(v);
        __nv_bfloat16 l = __float2bfloat16(v - __bfloat162float(h));
        g_dT_hi[(size_t)i * RANK + r] = h;
        g_dT_lo[(size_t)i * RANK + r] = l;
    }
}

// ==================== k2: mma.sync bf16 split GEMM, 128x128 CTA, warp 64x64 ====================
// grid(32 i-tiles[N=128], 86 o-tiles[M=128]), 128 threads = 4 warps (2m x 2n), warp 64x64.
// ldsm ratio 6 MMA/ldsm (vs 4 at 64x32); B rows permuted for coalesced epilogue.
#define A_HI 0          // 128 rows x 128B = 16KB
#define A_LO 16384
#define B_HI 32768      // 128 rows x 128B = 16KB
#define B_LO 49152
#define K2_SMEM 65536

__global__ __launch_bounds__(128) void k2_mma(
    const int* __restrict__ weight,
    const float* __restrict__ scale,
    const float* __restrict__ zp)
{
    extern __shared__ char smem[];
    __shared__ int s_rmax[128];
    const uint32_t sb = smem_to_u32(smem);
    const int tid = threadIdx.x;
    const int wid = tid >> 5;
    const int lane = tid & 31;
    const int i0 = blockIdx.x * 128;
    const int o0 = blockIdx.y * 128;

    s_rmax[tid] = 0;

    const int wm = (wid & 1) * 64;
    const int wn = (wid >> 1) * 64;

    float c[4][8][4];   // [mi 16-row][ni 8-col of 64][frag]
    #pragma unroll
    for (int mi = 0; mi < 4; ++mi)
        #pragma unroll
        for (int ni = 0; ni < 8; ++ni)
            #pragma unroll
            for (int q = 0; q < 4; ++q) c[mi][ni][q] = 0.f;

    const int a_row = (lane & 15);
    const int a_ch  = (lane >> 4);
    const int b_row = (lane & 7) + ((lane >> 4) << 3);
    const int b_ch  = (lane >> 3) & 1;

    #pragma unroll 1
    for (int kc = 0; kc < 2; ++kc) {
        // ---- stage A chunk (128 rows x 64 k-elems, hi+lo) ----
        #pragma unroll
        for (int j = 0; j < 8; ++j) {
            int idx = tid + j * 128;
            int row = idx >> 3;
            int ch = idx & 7;
            uint32_t dst = swz128((uint32_t)(row * 128 + ch * 16));
            size_t src = (size_t)(o0 + row) * 256 + kc * 128 + ch * 16;
            *reinterpret_cast<uint4*>(smem + A_HI + dst) =
                *reinterpret_cast<const uint4*>(reinterpret_cast<const char*>(g_up_hi) + src);
            *reinterpret_cast<uint4*>(smem + A_LO + dst) =
                *reinterpret_cast<const uint4*>(reinterpret_cast<const char*>(g_up_lo) + src);
        }
        // ---- stage B chunk (128 rows x 64 k-elems, hi+lo), PERMUTED rows ----
        #pragma unroll
        for (int j = 0; j < 8; ++j) {
            int idx = tid + j * 128;
            int row = idx >> 3;          // logical column index within tile
            int ch = idx & 7;
            int prow = bperm(row);       // permuted smem row
            uint32_t dst = swz128((uint32_t)(prow * 128 + ch * 16));
            size_t src = (size_t)(i0 + row) * 256 + kc * 128 + ch * 16;
            *reinterpret_cast<uint4*>(smem + B_HI + dst) =
                *reinterpret_cast<const uint4*>(reinterpret_cast<const char*>(g_dT_hi) + src);
            *reinterpret_cast<uint4*>(smem + B_LO + dst) =
                *reinterpret_cast<const uint4*>(reinterpret_cast<const char*>(g_dT_lo) + src);
        }
        __syncthreads();

        #pragma unroll
        for (int ks = 0; ks < 4; ++ks) {
            uint32_t bh[4][4], bl[4][4];
            #pragma unroll
            for (int g = 0; g < 4; ++g) {
                uint32_t off = swz128((uint32_t)((wn + g * 16 + b_row) * 128 + (ks * 2 + b_ch) * 16));
                ldsm_x4(bh[g], sb + B_HI + off);
                ldsm_x4(bl[g], sb + B_LO + off);
            }
            #pragma unroll
            for (int mi = 0; mi < 4; ++mi) {
                uint32_t ah[4], al[4];
                uint32_t off = swz128((uint32_t)((wm + mi * 16 + a_row) * 128 + (ks * 2 + a_ch) * 16));
                ldsm_x4(ah, sb + A_HI + off);
                ldsm_x4(al, sb + A_LO + off);
                #pragma unroll
                for (int ni = 0; ni < 8; ++ni) {
                    const int g = ni >> 1, h = (ni & 1) * 2;
                    mma_bf16(c[mi][ni], ah, bh[g][h], bh[g][h + 1]);   // hi*hi
                    mma_bf16(c[mi][ni], al, bh[g][h], bh[g][h + 1]);   // lo*hi
                    mma_bf16(c[mi][ni], ah, bl[g][h], bl[g][h + 1]);   // hi*lo
                }
            }
        }
        __syncthreads();   // all ldsm done before next chunk overwrites
    }

    // ---- coalesced fused epilogue: lane p owns logical cols [8p,8p+8) in each 32-group ----
    // logical col (in-group) = 8p + 2n + b  <->  accumulator c[mi][g32*4 + n][half*2 + b]
    const int gq = blockIdx.x;    // i-tile width 128 == quant group
    const int p = lane & 3;
    #pragma unroll
    for (int mi = 0; mi < 4; ++mi) {
        #pragma unroll
        for (int half = 0; half < 2; ++half) {
            const int rloc = wm + mi * 16 + (lane >> 2) + half * 8;
            const int o = o0 + rloc;
            const int h2 = half * 2;
            const float zpv = zp[o * NG + gq];
            const float scv = scale[o * NG + gq];
            float mx = 0.f;
            #pragma unroll
            for (int g32 = 0; g32 < 2; ++g32) {
                const int nb = g32 * 4;
                const size_t base = (size_t)o * IN_DIM + i0 + wn + g32 * 32 + p * 8;
                int4 w0 = *reinterpret_cast<const int4*>(&weight[base]);
                int4 w1 = *reinterpret_cast<const int4*>(&weight[base + 4]);
                float4 r0, r1;
                r0.x = fmaf((float)w0.x - zpv, scv, c[mi][nb + 0][h2]);
                r0.y = fmaf((float)w0.y - zpv, scv, c[mi][nb + 0][h2 + 1]);
                r0.z = fmaf((float)w0.z - zpv, scv, c[mi][nb + 1][h2]);
                r0.w = fmaf((float)w0.w - zpv, scv, c[mi][nb + 1][h2 + 1]);
                r1.x = fmaf((float)w1.x - zpv, scv, c[mi][nb + 2][h2]);
                r1.y = fmaf((float)w1.y - zpv, scv, c[mi][nb + 2][h2 + 1]);
                r1.z = fmaf((float)w1.z - zpv, scv, c[mi][nb + 3][h2]);
                r1.w = fmaf((float)w1.w - zpv, scv, c[mi][nb + 3][h2 + 1]);
                mx = fmaxf(mx,
                     fmaxf(fmaxf(fmaxf(fabsf(r0.x), fabsf(r0.y)), fmaxf(fabsf(r0.z), fabsf(r0.w))),
                           fmaxf(fmaxf(fabsf(r1.x), fabsf(r1.y)), fmaxf(fabsf(r1.z), fabsf(r1.w)))));
                *reinterpret_cast<float4*>(&g_Wf[base]) = r0;
                *reinterpret_cast<float4*>(&g_Wf[base + 4]) = r1;
            }
            atomicMax(&s_rmax[rloc], __float_as_int(mx));
        }
    }
    __syncthreads();
    atomicMax(&g_rowmax[o0 + tid], s_rmax[tid]);
}

// ==================== k2b: per-row quant multiplier ====================
__global__ void k2b_rowrcp() {
    int o = blockIdx.x * 256 + threadIdx.x;
    if (o < OUT_DIM) {
        float s = __fdiv_rn(__int_as_float(g_rowmax[o]), 127.0f);
        g_rcpw[o] = __frcp_rn(s);
    }
}

// ==================== k3: s8 IMMA GEMM, K-split x8, latency-hidden, atomic reduce ====================
__device__ __forceinline__ int s8idx(int r, int chk, int w) {
    return r * 32 + ((chk ^ (r & 7)) << 2) + w;
}
__device__ __forceinline__ int sxoff(int r, int c32, int chk, int w) {
    return r * 128 + c32 * 32 + ((chk ^ (r & 7)) << 2) + w;
}

#define K3_SX   0          // 8192 u32 = 32KB
#define K3_SW   32768      // 2 x 2048 u32 = 16KB
#define K3_RCP  49152      // 64 floats
#define K3_SMEM 49408

__global__ __launch_bounds__(256) void k3_imma() {
    extern __shared__ char smem3[];
    uint32_t* s_x = reinterpret_cast<uint32_t*>(smem3 + K3_SX);
    uint32_t* s_w = reinterpret_cast<uint32_t*>(smem3 + K3_SW);
    float*  s_rcp = reinterpret_cast<float*>(smem3 + K3_RCP);

    const int o0 = blockIdx.x * 64;
    const int kb = blockIdx.y;
    const int tid = threadIdx.x;
    const int wid = tid >> 5;
    const int lane = tid & 31;
    const int m0 = (wid >> 2) * 32;
    const int n0 = (wid & 3) * 16;

    if (tid < 64) s_rcp[tid] = g_rcpw[o0 + tid];

    const float4* Wf4 = reinterpret_cast<const float4*>(g_Wf);

    float4 wreg[8];
    #pragma unroll
    for (int j = 0; j < 8; ++j) {
        int idx = tid + j * 256;
        int r = idx >> 5, p = idx & 31;
        wreg[j] = Wf4[(size_t)(o0 + r) * 1024 + kb * 128 + p];
    }
    #pragma unroll
    for (int j = 0; j < 32; ++j) {
        int idx = tid + j * 256;
        int r = idx >> 7, p = idx & 127;
        s_x[sxoff(r, p >> 5, (p & 31) >> 2, p & 3)] = (uint32_t)g_xq[r * NPACK + kb * 128 + p];
    }
    __syncthreads();

    int c[2][2][4];
    #pragma unroll
    for (int mt = 0; mt < 2; ++mt)
        #pragma unroll
        for (int nt = 0; nt < 2; ++nt)
            #pragma unroll
            for (int q = 0; q < 4; ++q) c[mt][nt][q] = 0;

    #pragma unroll 1
    for (int cv = 0; cv < 4; ++cv) {
        uint32_t* wb = s_w + (cv & 1) * 2048;
        #pragma unroll
        for (int j = 0; j < 8; ++j) {
            int idx = tid + j * 256;
            int r = idx >> 5, p = idx & 31;
            wb[s8idx(r, p >> 2, p & 3)] = (uint32_t)quant_pack4_mul(wreg[j], s_rcp[r]);
        }
        __syncthreads();

        if (cv < 3) {
            #pragma unroll
            for (int j = 0; j < 8; ++j) {
                int idx = tid + j * 256;
                int r = idx >> 5, p = idx & 31;
                wreg[j] = Wf4[(size_t)(o0 + r) * 1024 + kb * 128 + (cv + 1) * 32 + p];
            }
        }

        #pragma unroll
        for (int ks = 0; ks < 4; ++ks) {
            uint32_t a[2][4], b[2][2];
            #pragma unroll
            for (int mt = 0; mt < 2; ++mt) {
                int r = m0 + mt * 16 + (lane >> 2);
                a[mt][0] = s_x[sxoff(r,     cv, ks * 2,     lane & 3)];
                a[mt][1] = s_x[sxoff(r + 8, cv, ks * 2,     lane & 3)];
                a[mt][2] = s_x[sxoff(r,     cv, ks * 2 + 1, lane & 3)];
                a[mt][3] = s_x[sxoff(r + 8, cv, ks * 2 + 1, lane & 3)];
            }
            #pragma unroll
            for (int nt = 0; nt < 2; ++nt) {
                int n = n0 + nt * 8 + (lane >> 2);
                b[nt][0] = wb[s8idx(n, ks * 2,     lane & 3)];
                b[nt][1] = wb[s8idx(n, ks * 2 + 1, lane & 3)];
            }
            #pragma unroll
            for (int mt = 0; mt < 2; ++mt)
                #pragma unroll
                for (int nt = 0; nt < 2; ++nt)
                    mma_s8(c[mt][nt], a[mt], b[nt][0], b[nt][1]);
        }
    }

    // atomic int32 reduce into g_acc (exact, order-independent)
    #pragma unroll
    for (int nt = 0; nt < 2; ++nt) {
        const int o = o0 + n0 + nt * 8 + (lane & 3) * 2;
        #pragma unroll
        for (int mt = 0; mt < 2; ++mt) {
            const int t0 = m0 + mt * 16 + (lane >> 2);
            atomicAdd(&g_acc[t0 * OUT_DIM + o],           c[mt][nt][0]);
            atomicAdd(&g_acc[t0 * OUT_DIM + o + 1],       c[mt][nt][1]);
            atomicAdd(&g_acc[(t0 + 8) * OUT_DIM + o],     c[mt][nt][2]);
            atomicAdd(&g_acc[(t0 + 8) * OUT_DIM + o + 1], c[mt][nt][3]);
        }
    }
}

// ==================== k4: scale + bias epilogue (vectorized x4) ====================
__global__ void k4_out(const float* __restrict__ bias, float* __restrict__ out) {
    int o = (blockIdx.x * 256 + threadIdx.x) * 4;
    int t = blockIdx.y;
    if (o < OUT_DIM) {
        int4 s = *reinterpret_cast<const int4*>(&g_acc[t * OUT_DIM + o]);
        const float sx = g_scale_x[t];
        float4 b = *reinterpret_cast<const float4*>(&bias[o]);
        float4 r;
        r.x = ((float)s.x * sx) * __fdiv_rn(__int_as_float(g_rowmax[o + 0]), 127.0f) + b.x;
        r.y = ((float)s.y * sx) * __fdiv_rn(__int_as_float(g_rowmax[o + 1]), 127.0f) + b.y;
        r.z = ((float)s.z * sx) * __fdiv_rn(__int_as_float(g_rowmax[o + 2]), 127.0f) + b.z;
        r.w = ((float)s.w * sx) * __fdiv_rn(__int_as_float(g_rowmax[o + 3]), 127.0f) + b.w;
        *reinterpret_cast<float4*>(&out[(size_t)t * OUT_DIM + o]) = r;
    }
}

// ==================== launch ====================
extern "C" void kernel_launch(void* const* d_in, const int* in_sizes, int n_in,
                              void* d_out, int out_size)
{
    const float* x      = (const float*)d_in[0];
    const int*   weight = (const int*)  d_in[1];
    const float* scale  = (const float*)d_in[2];
    const float* zp     = (const float*)d_in[3];
    const float* up     = (const float*)d_in[4];
    const float* down   = (const float*)d_in[5];
    const float* bias   = (const float*)d_in[6];
    float* out = (float*)d_out;

    cudaFuncSetAttribute(k2_mma, cudaFuncAttributeMaxDynamicSharedMemorySize, K2_SMEM);
    cudaFuncSetAttribute(k3_imma, cudaFuncAttributeMaxDynamicSharedMemorySize, K3_SMEM);

    k1_quant_x<<<64, 256>>>(x);
    kp_split_up<<<(OUT_DIM * RANK / 4 + 255) / 256, 256>>>(up);
    kp_split_downT<<<dim3(IN_DIM / 32, RANK / 32), dim3(32, 8)>>>(down);
    k2_mma<<<dim3(32, 86), 128, K2_SMEM>>>(weight, scale, zp);
    k2b_rowrcp<<<(OUT_DIM + 255) / 256, 256>>>();
    k3_imma<<<dim3(172, KSPLIT), 256, K3_SMEM>>>();
    k4_out<<<dim3((OUT_DIM / 4 + 255) / 256, NTOK), 256>>>(bias, out);
}

// round 14
// speedup vs baseline: 1.0098x; 1.0098x over previous
#include <cuda_runtime.h>
#include <cuda_bf16.h>
#include <cstdint>

#define OUT_DIM 11008
#define IN_DIM  4096
#define RANK    128
#define NG      32
#define NTOK    64
#define NPACK   1024
#define KSPLIT  8

// -------- device scratch --------
__device__ float g_Wf[(size_t)OUT_DIM * IN_DIM];
__device__ int   g_rowmax[OUT_DIM];
__device__ float g_rcpw[OUT_DIM];
__device__ int   g_xq[NTOK * NPACK];
__device__ float g_scale_x[NTOK];
__device__ __nv_bfloat16 g_up_hi[(size_t)OUT_DIM * RANK];
__device__ __nv_bfloat16 g_up_lo[(size_t)OUT_DIM * RANK];
__device__ __nv_bfloat16 g_dT_hi[(size_t)IN_DIM * RANK];
__device__ __nv_bfloat16 g_dT_lo[(size_t)IN_DIM * RANK];
__device__ int   g_acc[NTOK * OUT_DIM];

// -------- helpers --------
__device__ __forceinline__ uint32_t smem_to_u32(const void* p) {
    uint32_t a;
    asm("{ .reg .u64 t; cvta.to.shared.u64 t, %1; cvt.u32.u64 %0, t; }" : "=r"(a) : "l"(p));
    return a;
}
__device__ __forceinline__ void ldsm_x4(uint32_t (&r)[4], uint32_t addr) {
    asm volatile("ldmatrix.sync.aligned.m8n8.x4.shared.b16 {%0,%1,%2,%3}, [%4];"
        : "=r"(r[0]), "=r"(r[1]), "=r"(r[2]), "=r"(r[3]) : "r"(addr));
}
__device__ __forceinline__ void mma_bf16(float (&c)[4], const uint32_t (&a)[4],
                                         uint32_t b0, uint32_t b1) {
    asm volatile("mma.sync.aligned.m16n8k16.row.col.f32.bf16.bf16.f32 "
        "{%0,%1,%2,%3}, {%4,%5,%6,%7}, {%8,%9}, {%0,%1,%2,%3};"
        : "+f"(c[0]), "+f"(c[1]), "+f"(c[2]), "+f"(c[3])
        : "r"(a[0]), "r"(a[1]), "r"(a[2]), "r"(a[3]), "r"(b0), "r"(b1));
}
__device__ __forceinline__ void mma_s8(int (&c)[4], const uint32_t (&a)[4],
                                       uint32_t b0, uint32_t b1) {
    asm volatile("mma.sync.aligned.m16n8k32.row.col.s32.s8.s8.s32 "
        "{%0,%1,%2,%3}, {%4,%5,%6,%7}, {%8,%9}, {%0,%1,%2,%3};"
        : "+r"(c[0]), "+r"(c[1]), "+r"(c[2]), "+r"(c[3])
        : "r"(a[0]), "r"(a[1]), "r"(a[2]), "r"(a[3]), "r"(b0), "r"(b1));
}
// swizzle for 128B-pitch rows: XOR 16B-chunk index by row%8 (self-inverse)
__device__ __forceinline__ uint32_t swz128(uint32_t b) { return b ^ (((b >> 7) & 7u) << 4); }
// B-column permutation within each 32-row group: logical L = 8p+2n+b -> smem row 8n+2p+b.
__device__ __forceinline__ int bperm(int r) {
    return (r & ~31) | (((r >> 1) & 3) * 8 + ((r >> 3) & 3) * 2 + (r & 1));
}

__device__ __forceinline__ int quant_pack4_mul(float4 v, float rcp) {
    int q0 = __float2int_rn(v.x * rcp);
    int q1 = __float2int_rn(v.y * rcp);
    int q2 = __float2int_rn(v.z * rcp);
    int q3 = __float2int_rn(v.w * rcp);
    return (q0 & 0xff) | ((q1 & 0xff) << 8) | ((q2 & 0xff) << 16) | (q3 << 24);
}

// ==================== k1: quantize x, zero rowmax + g_acc ====================
__global__ void k1_quant_x(const float* __restrict__ x) {
    __shared__ __align__(16) float s_x[IN_DIM];
    __shared__ float s_red[256];
    const int t = blockIdx.x;
    const int tid = threadIdx.x;
    {
        int g = t * 256 + tid;
        if (g < OUT_DIM) g_rowmax[g] = 0;
        for (int z = g; z < NTOK * OUT_DIM; z += 64 * 256) g_acc[z] = 0;
    }
    const float4* xr = reinterpret_cast<const float4*>(x + (size_t)t * IN_DIM);
    float m = 0.f;
    #pragma unroll
    for (int j = 0; j < 4; ++j) {
        int idx = tid + j * 256;
        float4 v = xr[idx];
        reinterpret_cast<float4*>(s_x)[idx] = v;
        m = fmaxf(m, fmaxf(fmaxf(fabsf(v.x), fabsf(v.y)), fmaxf(fabsf(v.z), fabsf(v.w))));
    }
    s_red[tid] = m;
    __syncthreads();
    for (int s = 128; s > 0; s >>= 1) {
        if (tid < s) s_red[tid] = fmaxf(s_red[tid], s_red[tid + s]);
        __syncthreads();
    }
    const float sx = __fdiv_rn(s_red[0], 127.0f);
    if (tid == 0) g_scale_x[t] = sx;
    #pragma unroll
    for (int j = 0; j < 4; ++j) {
        int idx = tid + j * 256;
        float4 v = reinterpret_cast<const float4*>(s_x)[idx];
        int q0 = __float2int_rn(__fdiv_rn(v.x, sx));
        int q1 = __float2int_rn(__fdiv_rn(v.y, sx));
        int q2 = __float2int_rn(__fdiv_rn(v.z, sx));
        int q3 = __float2int_rn(__fdiv_rn(v.w, sx));
        g_xq[t * NPACK + idx] = (q0 & 0xff) | ((q1 & 0xff) << 8) | ((q2 & 0xff) << 16) | (q3 << 24);
    }
}

// ==================== prep: bf16 two-term splits ====================
__global__ void kp_split_up(const float* __restrict__ up) {
    int idx = blockIdx.x * 256 + threadIdx.x;
    if (idx < OUT_DIM * RANK / 4) {
        float4 v = reinterpret_cast<const float4*>(up)[idx];
        float f[4] = {v.x, v.y, v.z, v.w};
        uint32_t hi[2], lo[2];
        #pragma unroll
        for (int k = 0; k < 2; ++k) {
            __nv_bfloat16 h0 = __float2bfloat16(f[k*2+0]);
            __nv_bfloat16 h1 = __float2bfloat16(f[k*2+1]);
            __nv_bfloat16 l0 = __float2bfloat16(f[k*2+0] - __bfloat162float(h0));
            __nv_bfloat16 l1 = __float2bfloat16(f[k*2+1] - __bfloat162float(h1));
            hi[k] = (uint32_t)__bfloat16_as_ushort(h0) | ((uint32_t)__bfloat16_as_ushort(h1) << 16);
            lo[k] = (uint32_t)__bfloat16_as_ushort(l0) | ((uint32_t)__bfloat16_as_ushort(l1) << 16);
        }
        reinterpret_cast<uint2*>(g_up_hi)[idx] = make_uint2(hi[0], hi[1]);
        reinterpret_cast<uint2*>(g_up_lo)[idx] = make_uint2(lo[0], lo[1]);
    }
}

__global__ void kp_split_downT(const float* __restrict__ down) {
    __shared__ float t[32][33];
    const int bx = blockIdx.x, by = blockIdx.y;
    const int tx = threadIdx.x, ty = threadIdx.y;
    #pragma unroll
    for (int k = 0; k < 4; ++k)
        t[ty + k * 8][tx] = down[(size_t)(by * 32 + ty + k * 8) * IN_DIM + bx * 32 + tx];
    __syncthreads();
    #pragma unroll
    for (int k = 0; k < 4; ++k) {
        int i = bx * 32 + ty + k * 8;
        int r = by * 32 + tx;
        float v = t[tx][ty + k * 8];
        __nv_bfloat16 h = __float2bfloat16(v);
        __nv_bfloat16 l = __float2bfloat16(v - __bfloat162float(h));
        g_dT_hi[(size_t)i * RANK + r] = h;
        g_dT_lo[(size_t)i * RANK + r] = l;
    }
}

// ==================== k2: mma.sync bf16 split GEMM, 128x128 CTA, warp 64x64, reg-lean ====================
// grid(32 i-tiles[N=128], 86 o-tiles[M=128]), 128 threads = 4 warps (2m x 2n), warp 64x64.
// Per k-step: hold ALL A frags (32 regs) but only HALF the B frags (16 regs) at a time,
// processing n in two halves -> live set ~176 regs, no spills, 2 CTAs/SM.
#define A_HI 0          // 128 rows x 128B = 16KB
#define A_LO 16384
#define B_HI 32768      // 128 rows x 128B = 16KB
#define B_LO 49152
#define K2_SMEM 65536

__global__ __launch_bounds__(128) void k2_mma(
    const int* __restrict__ weight,
    const float* __restrict__ scale,
    const float* __restrict__ zp)
{
    extern __shared__ char smem[];
    __shared__ int s_rmax[128];
    const uint32_t sb = smem_to_u32(smem);
    const int tid = threadIdx.x;
    const int wid = tid >> 5;
    const int lane = tid & 31;
    const int i0 = blockIdx.x * 128;
    const int o0 = blockIdx.y * 128;

    s_rmax[tid] = 0;

    const int wm = (wid & 1) * 64;
    const int wn = (wid >> 1) * 64;

    float c[4][8][4];   // [mi 16-row][ni 8-col of 64][frag]
    #pragma unroll
    for (int mi = 0; mi < 4; ++mi)
        #pragma unroll
        for (int ni = 0; ni < 8; ++ni)
            #pragma unroll
            for (int q = 0; q < 4; ++q) c[mi][ni][q] = 0.f;

    const int a_row = (lane & 15);
    const int a_ch  = (lane >> 4);
    const int b_row = (lane & 7) + ((lane >> 4) << 3);
    const int b_ch  = (lane >> 3) & 1;

    #pragma unroll 1
    for (int kc = 0; kc < 2; ++kc) {
        // ---- stage A chunk (128 rows x 64 k-elems, hi+lo) ----
        #pragma unroll
        for (int j = 0; j < 8; ++j) {
            int idx = tid + j * 128;
            int row = idx >> 3;
            int ch = idx & 7;
            uint32_t dst = swz128((uint32_t)(row * 128 + ch * 16));
            size_t src = (size_t)(o0 + row) * 256 + kc * 128 + ch * 16;
            *reinterpret_cast<uint4*>(smem + A_HI + dst) =
                *reinterpret_cast<const uint4*>(reinterpret_cast<const char*>(g_up_hi) + src);
            *reinterpret_cast<uint4*>(smem + A_LO + dst) =
                *reinterpret_cast<const uint4*>(reinterpret_cast<const char*>(g_up_lo) + src);
        }
        // ---- stage B chunk (128 rows x 64 k-elems, hi+lo), PERMUTED rows ----
        #pragma unroll
        for (int j = 0; j < 8; ++j) {
            int idx = tid + j * 128;
            int row = idx >> 3;
            int ch = idx & 7;
            int prow = bperm(row);
            uint32_t dst = swz128((uint32_t)(prow * 128 + ch * 16));
            size_t src = (size_t)(i0 + row) * 256 + kc * 128 + ch * 16;
            *reinterpret_cast<uint4*>(smem + B_HI + dst) =
                *reinterpret_cast<const uint4*>(reinterpret_cast<const char*>(g_dT_hi) + src);
            *reinterpret_cast<uint4*>(smem + B_LO + dst) =
                *reinterpret_cast<const uint4*>(reinterpret_cast<const char*>(g_dT_lo) + src);
        }
        __syncthreads();

        #pragma unroll
        for (int ks = 0; ks < 4; ++ks) {
            // A frags for all 4 mi (held across both n-halves)
            uint32_t ah[4][4], al[4][4];
            #pragma unroll
            for (int mi = 0; mi < 4; ++mi) {
                uint32_t off = swz128((uint32_t)((wm + mi * 16 + a_row) * 128 + (ks * 2 + a_ch) * 16));
                ldsm_x4(ah[mi], sb + A_HI + off);
                ldsm_x4(al[mi], sb + A_LO + off);
            }
            // n-halves: only 2 B fragment groups live at a time
            #pragma unroll
            for (int half = 0; half < 2; ++half) {
                uint32_t bh[2][4], bl[2][4];
                #pragma unroll
                for (int g = 0; g < 2; ++g) {
                    uint32_t off = swz128((uint32_t)((wn + (half * 2 + g) * 16 + b_row) * 128
                                                     + (ks * 2 + b_ch) * 16));
                    ldsm_x4(bh[g], sb + B_HI + off);
                    ldsm_x4(bl[g], sb + B_LO + off);
                }
                #pragma unroll
                for (int mi = 0; mi < 4; ++mi)
                    #pragma unroll
                    for (int nn = 0; nn < 4; ++nn) {
                        const int ni = half * 4 + nn;
                        const int g = nn >> 1, h = (nn & 1) * 2;
                        mma_bf16(c[mi][ni], ah[mi], bh[g][h], bh[g][h + 1]);   // hi*hi
                        mma_bf16(c[mi][ni], al[mi], bh[g][h], bh[g][h + 1]);   // lo*hi
                        mma_bf16(c[mi][ni], ah[mi], bl[g][h], bl[g][h + 1]);   // hi*lo
                    }
            }
        }
        __syncthreads();   // all ldsm done before next chunk overwrites
    }

    // ---- coalesced fused epilogue: lane p owns logical cols [8p,8p+8) in each 32-group ----
    const int gq = blockIdx.x;    // i-tile width 128 == quant group
    const int p = lane & 3;
    #pragma unroll
    for (int mi = 0; mi < 4; ++mi) {
        #pragma unroll
        for (int half = 0; half < 2; ++half) {
            const int rloc = wm + mi * 16 + (lane >> 2) + half * 8;
            const int o = o0 + rloc;
            const int h2 = half * 2;
            const float zpv = zp[o * NG + gq];
            const float scv = scale[o * NG + gq];
            float mx = 0.f;
            #pragma unroll
            for (int g32 = 0; g32 < 2; ++g32) {
                const int nb = g32 * 4;
                const size_t base = (size_t)o * IN_DIM + i0 + wn + g32 * 32 + p * 8;
                int4 w0 = *reinterpret_cast<const int4*>(&weight[base]);
                int4 w1 = *reinterpret_cast<const int4*>(&weight[base + 4]);
                float4 r0, r1;
                r0.x = fmaf((float)w0.x - zpv, scv, c[mi][nb + 0][h2]);
                r0.y = fmaf((float)w0.y - zpv, scv, c[mi][nb + 0][h2 + 1]);
                r0.z = fmaf((float)w0.z - zpv, scv, c[mi][nb + 1][h2]);
                r0.w = fmaf((float)w0.w - zpv, scv, c[mi][nb + 1][h2 + 1]);
                r1.x = fmaf((float)w1.x - zpv, scv, c[mi][nb + 2][h2]);
                r1.y = fmaf((float)w1.y - zpv, scv, c[mi][nb + 2][h2 + 1]);
                r1.z = fmaf((float)w1.z - zpv, scv, c[mi][nb + 3][h2]);
                r1.w = fmaf((float)w1.w - zpv, scv, c[mi][nb + 3][h2 + 1]);
                mx = fmaxf(mx,
                     fmaxf(fmaxf(fmaxf(fabsf(r0.x), fabsf(r0.y)), fmaxf(fabsf(r0.z), fabsf(r0.w))),
                           fmaxf(fmaxf(fabsf(r1.x), fabsf(r1.y)), fmaxf(fabsf(r1.z), fabsf(r1.w)))));
                *reinterpret_cast<float4*>(&g_Wf[base]) = r0;
                *reinterpret_cast<float4*>(&g_Wf[base + 4]) = r1;
            }
            atomicMax(&s_rmax[rloc], __float_as_int(mx));
        }
    }
    __syncthreads();
    atomicMax(&g_rowmax[o0 + tid], s_rmax[tid]);
}

// ==================== k2b: per-row quant multiplier ====================
__global__ void k2b_rowrcp() {
    int o = blockIdx.x * 256 + threadIdx.x;
    if (o < OUT_DIM) {
        float s = __fdiv_rn(__int_as_float(g_rowmax[o]), 127.0f);
        g_rcpw[o] = __frcp_rn(s);
    }
}

// ==================== k3: s8 IMMA GEMM, K-split x8, latency-hidden, atomic reduce ====================
__device__ __forceinline__ int s8idx(int r, int chk, int w) {
    return r * 32 + ((chk ^ (r & 7)) << 2) + w;
}
__device__ __forceinline__ int sxoff(int r, int c32, int chk, int w) {
    return r * 128 + c32 * 32 + ((chk ^ (r & 7)) << 2) + w;
}

#define K3_SX   0          // 8192 u32 = 32KB
#define K3_SW   32768      // 2 x 2048 u32 = 16KB
#define K3_RCP  49152      // 64 floats
#define K3_SMEM 49408

__global__ __launch_bounds__(256) void k3_imma() {
    extern __shared__ char smem3[];
    uint32_t* s_x = reinterpret_cast<uint32_t*>(smem3 + K3_SX);
    uint32_t* s_w = reinterpret_cast<uint32_t*>(smem3 + K3_SW);
    float*  s_rcp = reinterpret_cast<float*>(smem3 + K3_RCP);

    const int o0 = blockIdx.x * 64;
    const int kb = blockIdx.y;
    const int tid = threadIdx.x;
    const int wid = tid >> 5;
    const int lane = tid & 31;
    const int m0 = (wid >> 2) * 32;
    const int n0 = (wid & 3) * 16;

    if (tid < 64) s_rcp[tid] = g_rcpw[o0 + tid];

    const float4* Wf4 = reinterpret_cast<const float4*>(g_Wf);

    float4 wreg[8];
    #pragma unroll
    for (int j = 0; j < 8; ++j) {
        int idx = tid + j * 256;
        int r = idx >> 5, p = idx & 31;
        wreg[j] = Wf4[(size_t)(o0 + r) * 1024 + kb * 128 + p];
    }
    #pragma unroll
    for (int j = 0; j < 32; ++j) {
        int idx = tid + j * 256;
        int r = idx >> 7, p = idx & 127;
        s_x[sxoff(r, p >> 5, (p & 31) >> 2, p & 3)] = (uint32_t)g_xq[r * NPACK + kb * 128 + p];
    }
    __syncthreads();

    int c[2][2][4];
    #pragma unroll
    for (int mt = 0; mt < 2; ++mt)
        #pragma unroll
        for (int nt = 0; nt < 2; ++nt)
            #pragma unroll
            for (int q = 0; q < 4; ++q) c[mt][nt][q] = 0;

    #pragma unroll 1
    for (int cv = 0; cv < 4; ++cv) {
        uint32_t* wb = s_w + (cv & 1) * 2048;
        #pragma unroll
        for (int j = 0; j < 8; ++j) {
            int idx = tid + j * 256;
            int r = idx >> 5, p = idx & 31;
            wb[s8idx(r, p >> 2, p & 3)] = (uint32_t)quant_pack4_mul(wreg[j], s_rcp[r]);
        }
        __syncthreads();

        if (cv < 3) {
            #pragma unroll
            for (int j = 0; j < 8; ++j) {
                int idx = tid + j * 256;
                int r = idx >> 5, p = idx & 31;
                wreg[j] = Wf4[(size_t)(o0 + r) * 1024 + kb * 128 + (cv + 1) * 32 + p];
            }
        }

        #pragma unroll
        for (int ks = 0; ks < 4; ++ks) {
            uint32_t a[2][4], b[2][2];
            #pragma unroll
            for (int mt = 0; mt < 2; ++mt) {
                int r = m0 + mt * 16 + (lane >> 2);
                a[mt][0] = s_x[sxoff(r,     cv, ks * 2,     lane & 3)];
                a[mt][1] = s_x[sxoff(r + 8, cv, ks * 2,     lane & 3)];
                a[mt][2] = s_x[sxoff(r,     cv, ks * 2 + 1, lane & 3)];
                a[mt][3] = s_x[sxoff(r + 8, cv, ks * 2 + 1, lane & 3)];
            }
            #pragma unroll
            for (int nt = 0; nt < 2; ++nt) {
                int n = n0 + nt * 8 + (lane >> 2);
                b[nt][0] = wb[s8idx(n, ks * 2,     lane & 3)];
                b[nt][1] = wb[s8idx(n, ks * 2 + 1, lane & 3)];
            }
            #pragma unroll
            for (int mt = 0; mt < 2; ++mt)
                #pragma unroll
                for (int nt = 0; nt < 2; ++nt)
                    mma_s8(c[mt][nt], a[mt], b[nt][0], b[nt][1]);
        }
    }

    // atomic int32 reduce into g_acc (exact, order-independent)
    #pragma unroll
    for (int nt = 0; nt < 2; ++nt) {
        const int o = o0 + n0 + nt * 8 + (lane & 3) * 2;
        #pragma unroll
        for (int mt = 0; mt < 2; ++mt) {
            const int t0 = m0 + mt * 16 + (lane >> 2);
            atomicAdd(&g_acc[t0 * OUT_DIM + o],           c[mt][nt][0]);
            atomicAdd(&g_acc[t0 * OUT_DIM + o + 1],       c[mt][nt][1]);
            atomicAdd(&g_acc[(t0 + 8) * OUT_DIM + o],     c[mt][nt][2]);
            atomicAdd(&g_acc[(t0 + 8) * OUT_DIM + o + 1], c[mt][nt][3]);
        }
    }
}

// ==================== k4: scale + bias epilogue (vectorized x4) ====================
__global__ void k4_out(const float* __restrict__ bias, float* __restrict__ out) {
    int o = (blockIdx.x * 256 + threadIdx.x) * 4;
    int t = blockIdx.y;
    if (o < OUT_DIM) {
        int4 s = *reinterpret_cast<const int4*>(&g_acc[t * OUT_DIM + o]);
        const float sx = g_scale_x[t];
        float4 b = *reinterpret_cast<const float4*>(&bias[o]);
        float4 r;
        r.x = ((float)s.x * sx) * __fdiv_rn(__int_as_float(g_rowmax[o + 0]), 127.0f) + b.x;
        r.y = ((float)s.y * sx) * __fdiv_rn(__int_as_float(g_rowmax[o + 1]), 127.0f) + b.y;
        r.z = ((float)s.z * sx) * __fdiv_rn(__int_as_float(g_rowmax[o + 2]), 127.0f) + b.z;
        r.w = ((float)s.w * sx) * __fdiv_rn(__int_as_float(g_rowmax[o + 3]), 127.0f) + b.w;
        *reinterpret_cast<float4*>(&out[(size_t)t * OUT_DIM + o]) = r;
    }
}

// ==================== launch ====================
extern "C" void kernel_launch(void* const* d_in, const int* in_sizes, int n_in,
                              void* d_out, int out_size)
{
    const float* x      = (const float*)d_in[0];
    const int*   weight = (const int*)  d_in[1];
    const float* scale  = (const float*)d_in[2];
    const float* zp     = (const float*)d_in[3];
    const float* up     = (const float*)d_in[4];
    const float* down   = (const float*)d_in[5];
    const float* bias   = (const float*)d_in[6];
    float* out = (float*)d_out;

    cudaFuncSetAttribute(k2_mma, cudaFuncAttributeMaxDynamicSharedMemorySize, K2_SMEM);
    cudaFuncSetAttribute(k3_imma, cudaFuncAttributeMaxDynamicSharedMemorySize, K3_SMEM);

    k1_quant_x<<<64, 256>>>(x);
    kp_split_up<<<(OUT_DIM * RANK / 4 + 255) / 256, 256>>>(up);
    kp_split_downT<<<dim3(IN_DIM / 32, RANK / 32), dim3(32, 8)>>>(down);
    k2_mma<<<dim3(32, 86), 128, K2_SMEM>>>(weight, scale, zp);
    k2b_rowrcp<<<(OUT_DIM + 255) / 256, 256>>>();
    k3_imma<<<dim3(172, KSPLIT), 256, K3_SMEM>>>();
    k4_out<<<dim3((OUT_DIM / 4 + 255) / 256, NTOK), 256>>>(bias, out);
}

// round 15
// speedup vs baseline: 1.0502x; 1.0400x over previous
#include <cuda_runtime.h>
#include <cuda_bf16.h>
#include <cstdint>

#define OUT_DIM 11008
#define IN_DIM  4096
#define RANK    128
#define NG      32
#define NTOK    64
#define NPACK   1024
#define KSPLIT  8

// -------- device scratch --------
__device__ float g_Wf[(size_t)OUT_DIM * IN_DIM];
__device__ int   g_rowmax[OUT_DIM];
__device__ float g_rcpw[OUT_DIM];
__device__ int   g_xq[NTOK * NPACK];
__device__ float g_scale_x[NTOK];
__device__ __nv_bfloat16 g_up_hi[(size_t)OUT_DIM * RANK];
__device__ __nv_bfloat16 g_up_lo[(size_t)OUT_DIM * RANK];
__device__ __nv_bfloat16 g_dT_hi[(size_t)IN_DIM * RANK];
__device__ __nv_bfloat16 g_dT_lo[(size_t)IN_DIM * RANK];
__device__ int   g_acc[NTOK * OUT_DIM];

// -------- helpers --------
__device__ __forceinline__ uint32_t smem_to_u32(const void* p) {
    uint32_t a;
    asm("{ .reg .u64 t; cvta.to.shared.u64 t, %1; cvt.u32.u64 %0, t; }" : "=r"(a) : "l"(p));
    return a;
}
__device__ __forceinline__ void ldsm_x4(uint32_t (&r)[4], uint32_t addr) {
    asm volatile("ldmatrix.sync.aligned.m8n8.x4.shared.b16 {%0,%1,%2,%3}, [%4];"
        : "=r"(r[0]), "=r"(r[1]), "=r"(r[2]), "=r"(r[3]) : "r"(addr));
}
__device__ __forceinline__ void mma_bf16(float (&c)[4], const uint32_t (&a)[4],
                                         uint32_t b0, uint32_t b1) {
    asm volatile("mma.sync.aligned.m16n8k16.row.col.f32.bf16.bf16.f32 "
        "{%0,%1,%2,%3}, {%4,%5,%6,%7}, {%8,%9}, {%0,%1,%2,%3};"
        : "+f"(c[0]), "+f"(c[1]), "+f"(c[2]), "+f"(c[3])
        : "r"(a[0]), "r"(a[1]), "r"(a[2]), "r"(a[3]), "r"(b0), "r"(b1));
}
__device__ __forceinline__ void mma_s8(int (&c)[4], const uint32_t (&a)[4],
                                       uint32_t b0, uint32_t b1) {
    asm volatile("mma.sync.aligned.m16n8k32.row.col.s32.s8.s8.s32 "
        "{%0,%1,%2,%3}, {%4,%5,%6,%7}, {%8,%9}, {%0,%1,%2,%3};"
        : "+r"(c[0]), "+r"(c[1]), "+r"(c[2]), "+r"(c[3])
        : "r"(a[0]), "r"(a[1]), "r"(a[2]), "r"(a[3]), "r"(b0), "r"(b1));
}
// swizzle for 128B-pitch rows: XOR 16B-chunk index by row%8 (self-inverse)
__device__ __forceinline__ uint32_t swz128(uint32_t b) { return b ^ (((b >> 7) & 7u) << 4); }
// B-column permutation within a 32-row group: logical L = 8p+2n+b -> smem row 8n+2p+b.
// Lane p of a quad then owns logical columns [8p, 8p+8) contiguously in the epilogue.
__device__ __forceinline__ int bperm(int r) {
    return (r & 32) | (((r >> 1) & 3) * 8 + ((r >> 3) & 3) * 2 + (r & 1));
}

__device__ __forceinline__ int quant_pack4_mul(float4 v, float rcp) {
    int q0 = __float2int_rn(v.x * rcp);
    int q1 = __float2int_rn(v.y * rcp);
    int q2 = __float2int_rn(v.z * rcp);
    int q3 = __float2int_rn(v.w * rcp);
    return (q0 & 0xff) | ((q1 & 0xff) << 8) | ((q2 & 0xff) << 16) | (q3 << 24);
}

// ==================== k1: quantize x, zero rowmax + g_acc ====================
__global__ void k1_quant_x(const float* __restrict__ x) {
    __shared__ __align__(16) float s_x[IN_DIM];
    __shared__ float s_red[256];
    const int t = blockIdx.x;
    const int tid = threadIdx.x;
    {
        int g = t * 256 + tid;
        if (g < OUT_DIM) g_rowmax[g] = 0;
        for (int z = g; z < NTOK * OUT_DIM; z += 64 * 256) g_acc[z] = 0;
    }
    const float4* xr = reinterpret_cast<const float4*>(x + (size_t)t * IN_DIM);
    float m = 0.f;
    #pragma unroll
    for (int j = 0; j < 4; ++j) {
        int idx = tid + j * 256;
        float4 v = xr[idx];
        reinterpret_cast<float4*>(s_x)[idx] = v;
        m = fmaxf(m, fmaxf(fmaxf(fabsf(v.x), fabsf(v.y)), fmaxf(fabsf(v.z), fabsf(v.w))));
    }
    s_red[tid] = m;
    __syncthreads();
    for (int s = 128; s > 0; s >>= 1) {
        if (tid < s) s_red[tid] = fmaxf(s_red[tid], s_red[tid + s]);
        __syncthreads();
    }
    const float sx = __fdiv_rn(s_red[0], 127.0f);
    if (tid == 0) g_scale_x[t] = sx;
    #pragma unroll
    for (int j = 0; j < 4; ++j) {
        int idx = tid + j * 256;
        float4 v = reinterpret_cast<const float4*>(s_x)[idx];
        int q0 = __float2int_rn(__fdiv_rn(v.x, sx));
        int q1 = __float2int_rn(__fdiv_rn(v.y, sx));
        int q2 = __float2int_rn(__fdiv_rn(v.z, sx));
        int q3 = __float2int_rn(__fdiv_rn(v.w, sx));
        g_xq[t * NPACK + idx] = (q0 & 0xff) | ((q1 & 0xff) << 8) | ((q2 & 0xff) << 16) | (q3 << 24);
    }
}

// ==================== fused prep: bf16 two-term splits (up + downT) ====================
#define UP_BLOCKS ((OUT_DIM * RANK / 4 + 255) / 256)     // 1376
#define DT_BLOCKS ((IN_DIM / 32) * (RANK / 32))          // 512

__global__ void kp_split(const float* __restrict__ up, const float* __restrict__ down) {
    if (blockIdx.x < UP_BLOCKS) {
        int idx = blockIdx.x * 256 + threadIdx.x;
        if (idx < OUT_DIM * RANK / 4) {
            float4 v = reinterpret_cast<const float4*>(up)[idx];
            float f[4] = {v.x, v.y, v.z, v.w};
            uint32_t hi[2], lo[2];
            #pragma unroll
            for (int k = 0; k < 2; ++k) {
                __nv_bfloat16 h0 = __float2bfloat16(f[k*2+0]);
                __nv_bfloat16 h1 = __float2bfloat16(f[k*2+1]);
                __nv_bfloat16 l0 = __float2bfloat16(f[k*2+0] - __bfloat162float(h0));
                __nv_bfloat16 l1 = __float2bfloat16(f[k*2+1] - __bfloat162float(h1));
                hi[k] = (uint32_t)__bfloat16_as_ushort(h0) | ((uint32_t)__bfloat16_as_ushort(h1) << 16);
                lo[k] = (uint32_t)__bfloat16_as_ushort(l0) | ((uint32_t)__bfloat16_as_ushort(l1) << 16);
            }
            reinterpret_cast<uint2*>(g_up_hi)[idx] = make_uint2(hi[0], hi[1]);
            reinterpret_cast<uint2*>(g_up_lo)[idx] = make_uint2(lo[0], lo[1]);
        }
    } else {
        __shared__ float t[32][33];
        const int blk = blockIdx.x - UP_BLOCKS;
        const int bx = blk % (IN_DIM / 32);
        const int by = blk / (IN_DIM / 32);
        const int tx = threadIdx.x & 31;
        const int ty = threadIdx.x >> 5;
        #pragma unroll
        for (int k = 0; k < 4; ++k)
            t[ty + k * 8][tx] = down[(size_t)(by * 32 + ty + k * 8) * IN_DIM + bx * 32 + tx];
        __syncthreads();
        #pragma unroll
        for (int k = 0; k < 4; ++k) {
            int i = bx * 32 + ty + k * 8;
            int r = by * 32 + tx;
            float v = t[tx][ty + k * 8];
            __nv_bfloat16 h = __float2bfloat16(v);
            __nv_bfloat16 l = __float2bfloat16(v - __bfloat162float(h));
            g_dT_hi[(size_t)i * RANK + r] = h;
            g_dT_lo[(size_t)i * RANK + r] = l;
        }
    }
}

// ==================== k2: mma.sync bf16 split GEMM (round-12 proven, 131.7us) ====================
// grid(64 i-tiles[N=64], 86 o-tiles[M=128]), 128 threads = 4 warps (2m x 2n), warp 64x32.
// Rank staged in 2 chunks of 64 (48KB); B rows permuted -> coalesced int4/float4 epilogue.
#define A_HI 0          // 128 rows x 128B = 16KB
#define A_LO 16384
#define B_HI 32768      // 64 rows x 128B = 8KB
#define B_LO 40960
#define K2_SMEM 49152

__global__ __launch_bounds__(128) void k2_mma(
    const int* __restrict__ weight,
    const float* __restrict__ scale,
    const float* __restrict__ zp)
{
    extern __shared__ char smem[];
    __shared__ int s_rmax[128];
    const uint32_t sb = smem_to_u32(smem);
    const int tid = threadIdx.x;
    const int wid = tid >> 5;
    const int lane = tid & 31;
    const int i0 = blockIdx.x * 64;
    const int o0 = blockIdx.y * 128;

    s_rmax[tid] = 0;

    const int wm = (wid & 1) * 64;
    const int wn = (wid >> 1) * 32;

    float c[4][4][4];
    #pragma unroll
    for (int mi = 0; mi < 4; ++mi)
        #pragma unroll
        for (int ni = 0; ni < 4; ++ni)
            #pragma unroll
            for (int q = 0; q < 4; ++q) c[mi][ni][q] = 0.f;

    const int a_row = (lane & 15);
    const int a_ch  = (lane >> 4);
    const int b_row = (lane & 7) + ((lane >> 4) << 3);
    const int b_ch  = (lane >> 3) & 1;

    #pragma unroll
    for (int kc = 0; kc < 2; ++kc) {
        // ---- stage A chunk (128 rows x 64 k-elems, hi+lo) ----
        #pragma unroll
        for (int j = 0; j < 8; ++j) {
            int idx = tid + j * 128;
            int row = idx >> 3;
            int ch = idx & 7;
            uint32_t dst = swz128((uint32_t)(row * 128 + ch * 16));
            size_t src = (size_t)(o0 + row) * 256 + kc * 128 + ch * 16;
            *reinterpret_cast<uint4*>(smem + A_HI + dst) =
                *reinterpret_cast<const uint4*>(reinterpret_cast<const char*>(g_up_hi) + src);
            *reinterpret_cast<uint4*>(smem + A_LO + dst) =
                *reinterpret_cast<const uint4*>(reinterpret_cast<const char*>(g_up_lo) + src);
        }
        // ---- stage B chunk (64 rows x 64 k-elems, hi+lo), PERMUTED rows ----
        #pragma unroll
        for (int j = 0; j < 4; ++j) {
            int idx = tid + j * 128;
            int row = idx >> 3;          // logical column index within tile
            int ch = idx & 7;
            int prow = bperm(row);       // permuted smem row
            uint32_t dst = swz128((uint32_t)(prow * 128 + ch * 16));
            size_t src = (size_t)(i0 + row) * 256 + kc * 128 + ch * 16;
            *reinterpret_cast<uint4*>(smem + B_HI + dst) =
                *reinterpret_cast<const uint4*>(reinterpret_cast<const char*>(g_dT_hi) + src);
            *reinterpret_cast<uint4*>(smem + B_LO + dst) =
                *reinterpret_cast<const uint4*>(reinterpret_cast<const char*>(g_dT_lo) + src);
        }
        __syncthreads();

        #pragma unroll
        for (int ks = 0; ks < 4; ++ks) {
            uint32_t ah[4][4], al[4][4], bh[2][4], bl[2][4];
            #pragma unroll
            for (int mi = 0; mi < 4; ++mi) {
                uint32_t off = swz128((uint32_t)((wm + mi * 16 + a_row) * 128 + (ks * 2 + a_ch) * 16));
                ldsm_x4(ah[mi], sb + A_HI + off);
                ldsm_x4(al[mi], sb + A_LO + off);
            }
            #pragma unroll
            for (int g = 0; g < 2; ++g) {
                uint32_t off = swz128((uint32_t)((wn + g * 16 + b_row) * 128 + (ks * 2 + b_ch) * 16));
                ldsm_x4(bh[g], sb + B_HI + off);
                ldsm_x4(bl[g], sb + B_LO + off);
            }
            #pragma unroll
            for (int mi = 0; mi < 4; ++mi)
                #pragma unroll
                for (int ni = 0; ni < 4; ++ni) {
                    const int g = ni >> 1, h = (ni & 1) * 2;
                    mma_bf16(c[mi][ni], ah[mi], bh[g][h], bh[g][h + 1]);   // hi*hi
                    mma_bf16(c[mi][ni], al[mi], bh[g][h], bh[g][h + 1]);   // lo*hi
                    mma_bf16(c[mi][ni], ah[mi], bl[g][h], bl[g][h + 1]);   // hi*lo
                }
        }
        __syncthreads();   // all ldsm done before next chunk overwrites
    }

    // ---- coalesced fused epilogue: lane p owns logical cols [8p, 8p+8) ----
    // logical col L = 8p + 2*ni + b  <->  accumulator c[mi][ni][half*2 + b]
    const int gq = blockIdx.x >> 1;
    const int p = lane & 3;
    #pragma unroll
    for (int mi = 0; mi < 4; ++mi) {
        #pragma unroll
        for (int half = 0; half < 2; ++half) {
            const int rloc = wm + mi * 16 + (lane >> 2) + half * 8;
            const int o = o0 + rloc;
            const int h2 = half * 2;
            const float zpv = zp[o * NG + gq];
            const float scv = scale[o * NG + gq];
            const size_t base = (size_t)o * IN_DIM + i0 + wn + p * 8;
            int4 w0 = *reinterpret_cast<const int4*>(&weight[base]);
            int4 w1 = *reinterpret_cast<const int4*>(&weight[base + 4]);
            float4 r0, r1;
            r0.x = fmaf((float)w0.x - zpv, scv, c[mi][0][h2]);
            r0.y = fmaf((float)w0.y - zpv, scv, c[mi][0][h2 + 1]);
            r0.z = fmaf((float)w0.z - zpv, scv, c[mi][1][h2]);
            r0.w = fmaf((float)w0.w - zpv, scv, c[mi][1][h2 + 1]);
            r1.x = fmaf((float)w1.x - zpv, scv, c[mi][2][h2]);
            r1.y = fmaf((float)w1.y - zpv, scv, c[mi][2][h2 + 1]);
            r1.z = fmaf((float)w1.z - zpv, scv, c[mi][3][h2]);
            r1.w = fmaf((float)w1.w - zpv, scv, c[mi][3][h2 + 1]);
            float mx = fmaxf(fmaxf(fmaxf(fabsf(r0.x), fabsf(r0.y)), fmaxf(fabsf(r0.z), fabsf(r0.w))),
                             fmaxf(fmaxf(fabsf(r1.x), fabsf(r1.y)), fmaxf(fabsf(r1.z), fabsf(r1.w))));
            atomicMax(&s_rmax[rloc], __float_as_int(mx));
            *reinterpret_cast<float4*>(&g_Wf[base]) = r0;
            *reinterpret_cast<float4*>(&g_Wf[base + 4]) = r1;
        }
    }
    __syncthreads();
    atomicMax(&g_rowmax[o0 + tid], s_rmax[tid]);
}

// ==================== k2b: per-row quant multiplier ====================
__global__ void k2b_rowrcp() {
    int o = blockIdx.x * 256 + threadIdx.x;
    if (o < OUT_DIM) {
        float s = __fdiv_rn(__int_as_float(g_rowmax[o]), 127.0f);
        g_rcpw[o] = __frcp_rn(s);
    }
}

// ==================== k3: s8 IMMA GEMM, K-split x8, latency-hidden, atomic reduce ====================
__device__ __forceinline__ int s8idx(int r, int chk, int w) {
    return r * 32 + ((chk ^ (r & 7)) << 2) + w;
}
__device__ __forceinline__ int sxoff(int r, int c32, int chk, int w) {
    return r * 128 + c32 * 32 + ((chk ^ (r & 7)) << 2) + w;
}

#define K3_SX   0          // 8192 u32 = 32KB
#define K3_SW   32768      // 2 x 2048 u32 = 16KB
#define K3_RCP  49152      // 64 floats
#define K3_SMEM 49408

__global__ __launch_bounds__(256) void k3_imma() {
    extern __shared__ char smem3[];
    uint32_t* s_x = reinterpret_cast<uint32_t*>(smem3 + K3_SX);
    uint32_t* s_w = reinterpret_cast<uint32_t*>(smem3 + K3_SW);
    float*  s_rcp = reinterpret_cast<float*>(smem3 + K3_RCP);

    const int o0 = blockIdx.x * 64;
    const int kb = blockIdx.y;
    const int tid = threadIdx.x;
    const int wid = tid >> 5;
    const int lane = tid & 31;
    const int m0 = (wid >> 2) * 32;
    const int n0 = (wid & 3) * 16;

    if (tid < 64) s_rcp[tid] = g_rcpw[o0 + tid];

    const float4* Wf4 = reinterpret_cast<const float4*>(g_Wf);

    float4 wreg[8];
    #pragma unroll
    for (int j = 0; j < 8; ++j) {
        int idx = tid + j * 256;
        int r = idx >> 5, p = idx & 31;
        wreg[j] = Wf4[(size_t)(o0 + r) * 1024 + kb * 128 + p];
    }
    #pragma unroll
    for (int j = 0; j < 32; ++j) {
        int idx = tid + j * 256;
        int r = idx >> 7, p = idx & 127;
        s_x[sxoff(r, p >> 5, (p & 31) >> 2, p & 3)] = (uint32_t)g_xq[r * NPACK + kb * 128 + p];
    }
    __syncthreads();

    int c[2][2][4];
    #pragma unroll
    for (int mt = 0; mt < 2; ++mt)
        #pragma unroll
        for (int nt = 0; nt < 2; ++nt)
            #pragma unroll
            for (int q = 0; q < 4; ++q) c[mt][nt][q] = 0;

    #pragma unroll 1
    for (int cv = 0; cv < 4; ++cv) {
        uint32_t* wb = s_w + (cv & 1) * 2048;
        #pragma unroll
        for (int j = 0; j < 8; ++j) {
            int idx = tid + j * 256;
            int r = idx >> 5, p = idx & 31;
            wb[s8idx(r, p >> 2, p & 3)] = (uint32_t)quant_pack4_mul(wreg[j], s_rcp[r]);
        }
        __syncthreads();

        if (cv < 3) {
            #pragma unroll
            for (int j = 0; j < 8; ++j) {
                int idx = tid + j * 256;
                int r = idx >> 5, p = idx & 31;
                wreg[j] = Wf4[(size_t)(o0 + r) * 1024 + kb * 128 + (cv + 1) * 32 + p];
            }
        }

        #pragma unroll
        for (int ks = 0; ks < 4; ++ks) {
            uint32_t a[2][4], b[2][2];
            #pragma unroll
            for (int mt = 0; mt < 2; ++mt) {
                int r = m0 + mt * 16 + (lane >> 2);
                a[mt][0] = s_x[sxoff(r,     cv, ks * 2,     lane & 3)];
                a[mt][1] = s_x[sxoff(r + 8, cv, ks * 2,     lane & 3)];
                a[mt][2] = s_x[sxoff(r,     cv, ks * 2 + 1, lane & 3)];
                a[mt][3] = s_x[sxoff(r + 8, cv, ks * 2 + 1, lane & 3)];
            }
            #pragma unroll
            for (int nt = 0; nt < 2; ++nt) {
                int n = n0 + nt * 8 + (lane >> 2);
                b[nt][0] = wb[s8idx(n, ks * 2,     lane & 3)];
                b[nt][1] = wb[s8idx(n, ks * 2 + 1, lane & 3)];
            }
            #pragma unroll
            for (int mt = 0; mt < 2; ++mt)
                #pragma unroll
                for (int nt = 0; nt < 2; ++nt)
                    mma_s8(c[mt][nt], a[mt], b[nt][0], b[nt][1]);
        }
    }

    // atomic int32 reduce into g_acc (exact, order-independent)
    #pragma unroll
    for (int nt = 0; nt < 2; ++nt) {
        const int o = o0 + n0 + nt * 8 + (lane & 3) * 2;
        #pragma unroll
        for (int mt = 0; mt < 2; ++mt) {
            const int t0 = m0 + mt * 16 + (lane >> 2);
            atomicAdd(&g_acc[t0 * OUT_DIM + o],           c[mt][nt][0]);
            atomicAdd(&g_acc[t0 * OUT_DIM + o + 1],       c[mt][nt][1]);
            atomicAdd(&g_acc[(t0 + 8) * OUT_DIM + o],     c[mt][nt][2]);
            atomicAdd(&g_acc[(t0 + 8) * OUT_DIM + o + 1], c[mt][nt][3]);
        }
    }
}

// ==================== k4: scale + bias epilogue (vectorized x4) ====================
__global__ void k4_out(const float* __restrict__ bias, float* __restrict__ out) {
    int o = (blockIdx.x * 256 + threadIdx.x) * 4;
    int t = blockIdx.y;
    if (o < OUT_DIM) {
        int4 s = *reinterpret_cast<const int4*>(&g_acc[t * OUT_DIM + o]);
        const float sx = g_scale_x[t];
        float4 b = *reinterpret_cast<const float4*>(&bias[o]);
        float4 r;
        r.x = ((float)s.x * sx) * __fdiv_rn(__int_as_float(g_rowmax[o + 0]), 127.0f) + b.x;
        r.y = ((float)s.y * sx) * __fdiv_rn(__int_as_float(g_rowmax[o + 1]), 127.0f) + b.y;
        r.z = ((float)s.z * sx) * __fdiv_rn(__int_as_float(g_rowmax[o + 2]), 127.0f) + b.z;
        r.w = ((float)s.w * sx) * __fdiv_rn(__int_as_float(g_rowmax[o + 3]), 127.0f) + b.w;
        *reinterpret_cast<float4*>(&out[(size_t)t * OUT_DIM + o]) = r;
    }
}

// ==================== launch ====================
extern "C" void kernel_launch(void* const* d_in, const int* in_sizes, int n_in,
                              void* d_out, int out_size)
{
    const float* x      = (const float*)d_in[0];
    const int*   weight = (const int*)  d_in[1];
    const float* scale  = (const float*)d_in[2];
    const float* zp     = (const float*)d_in[3];
    const float* up     = (const float*)d_in[4];
    const float* down   = (const float*)d_in[5];
    const float* bias   = (const float*)d_in[6];
    float* out = (float*)d_out;

    cudaFuncSetAttribute(k2_mma, cudaFuncAttributeMaxDynamicSharedMemorySize, K2_SMEM);
    cudaFuncSetAttribute(k3_imma, cudaFuncAttributeMaxDynamicSharedMemorySize, K3_SMEM);

    k1_quant_x<<<64, 256>>>(x);
    kp_split<<<UP_BLOCKS + DT_BLOCKS, 256>>>(up, down);
    k2_mma<<<dim3(64, 86), 128, K2_SMEM>>>(weight, scale, zp);
    k2b_rowrcp<<<(OUT_DIM + 255) / 256, 256>>>();
    k3_imma<<<dim3(172, KSPLIT), 256, K3_SMEM>>>();
    k4_out<<<dim3((OUT_DIM / 4 + 255) / 256, NTOK), 256>>>(bias, out);
}